// round 4
// baseline (speedup 1.0000x reference)
#include <cuda_runtime.h>

// ---------------------------------------------------------------------------
// MatrixRouting (EM routing, matrix capsules)
//   b=8, Bkk=288, Cww=1152, hh=17, C=32, w=6, NUM_ROUTING=3
// Outputs (concatenated in d_out):
//   mu_a : (8, 32, 6, 6, 17)        = 156672 floats
//   R    : (8, 288, 32, 6, 6)       = 2654208 floats
//   votes: (8, 288, 1152, 17)       = 45121536 floats (passthrough)
// ---------------------------------------------------------------------------

#define EPSV        1e-10f
#define LAMBDA_C    1e-4f
#define HALF_LN_2PI 0.918938533204672741780329736406f

constexpr int B    = 8;
constexpr int BKK  = 288;
constexpr int CWW  = 1152;
constexpr int HH   = 17;
constexpr int NV   = 16;        // hh - 1
constexpr int NCAP = 32;        // OUTPUT_DIM
constexpr int PP   = 36;        // w*w

constexpr int MU_A_SIZE = B * NCAP * PP * HH;     // 156672
constexpr int R_SIZE    = B * BKK * CWW;          // 2654208
constexpr int MU_A_OFF  = 0;
constexpr int R_OFF     = MU_A_SIZE;
constexpr int VOTES_OFF = MU_A_SIZE + R_SIZE;

// scratch (no cudaMalloc allowed)
__device__ float g_ap[B * BKK * CWW];   // ap (and R carrier), layout (b, i, j)
__device__ float g_S[B * BKK];          // ap.sum over j

// ---------------------------------------------------------------------------
// M-step kernel: one CTA per (b, j) column.
// MODE 0: first iteration  (R = 1/32)     ; fuses votes passthrough; writes ap
// MODE 1: middle iteration (R from ap/S)  ; writes ap (in place, column-local)
// MODE 2: last iteration   (R from ap/S)  ; writes mu_a and R_out (= R*a_)
// ---------------------------------------------------------------------------
template <int MODE>
__global__ __launch_bounds__(256)
void mstep(const float* __restrict__ votes,
           const float* __restrict__ beta_v,
           const float* __restrict__ beta_a,
           float* __restrict__ out)
{
    __shared__ float sv[BKK * 17];     // V rows padded to 17; [i*17+16] = a_
    __shared__ float sRw[BKK];         // R * a_
    __shared__ float spart[256];       // reduction scratch
    __shared__ float smu[NV];
    __shared__ float sn2s[NV];         // -1/(2 sigma^2)
    __shared__ float slnc[NV];         // -log_sigma - 0.5*ln(2pi)
    __shared__ float sls[NV];          // log_sigma
    __shared__ float ssumR;
    __shared__ float sa;

    const int j = blockIdx.x;          // 0..1151
    const int b = blockIdx.y;          // 0..7
    const int t = threadIdx.x;

    // votes[b, i, j, h] = votes[base + i*(CWW*HH) + h]
    const int base = b * (BKK * CWW * HH) + j * HH;

    // ---- load column into smem (and passthrough copy on MODE 0) ----
    float* votes_out = out + VOTES_OFF;
    for (int e = t; e < BKK * 17; e += 256) {
        int i = e / 17;
        int h = e - i * 17;
        int gidx = base + i * (CWW * HH) + h;
        float v = votes[gidx];
        sv[e] = v;                      // padded row stride 17 == linear e
        if (MODE == 0) votes_out[gidx] = v;
    }
    __syncthreads();

    // ---- Rw = R * a_ ----
    const float* apcol = g_ap + b * (BKK * CWW) + j;
    for (int i = t; i < BKK; i += 256) {
        float av = sv[i * 17 + 16];
        float r;
        if (MODE == 0) {
            r = av * (1.0f / 32.0f);
        } else {
            float ap = apcol[i * CWW];
            float S  = g_S[b * BKK + i];
            r = (ap / (S + EPSV) + EPSV) * av;
        }
        sRw[i] = r;
    }
    __syncthreads();

    // ---- mu numerators: 16 h-columns x 16 groups ----
    {
        int h = t & 15, g = t >> 4;
        float acc = 0.f;
        for (int i = g; i < BKK; i += 16)
            acc += sRw[i] * sv[i * 17 + h];
        spart[t] = acc;
    }
    __syncthreads();

    // numerators (t<16) and sum_R (warp 1) concurrently
    if (t < 16) {
        float s = 0.f;
        #pragma unroll
        for (int g = 0; g < 16; g++) s += spart[g * 16 + t];
        smu[t] = s;                    // numerator; divide after ssumR ready
    }
    if ((t >> 5) == 1) {
        int l = t & 31;
        float s = 0.f;
        for (int i = l; i < BKK; i += 32) s += sRw[i];
        #pragma unroll
        for (int o = 16; o; o >>= 1) s += __shfl_down_sync(0xffffffffu, s, o);
        if (l == 0) ssumR = s + 1e-4f;
    }
    __syncthreads();

    if (t < 16) smu[t] = smu[t] / ssumR;
    __syncthreads();

    // ---- sigma^2 ----
    {
        int h = t & 15, g = t >> 4;
        float m = smu[h];
        float acc = 0.f;
        for (int i = g; i < BKK; i += 16) {
            float d = sv[i * 17 + h] - m;
            acc += sRw[i] * (d * d + EPSV);
        }
        spart[t] = acc;
    }
    __syncthreads();

    if (t < 16) {
        float s = 0.f;
        #pragma unroll
        for (int g = 0; g < 16; g++) s += spart[g * 16 + t];
        float sig = s / ssumR + EPSV;               // sigma_square
        float ls  = __logf(sqrtf(sig) + EPSV);      // log_sigma
        sls[t]  = ls;
        sn2s[t] = -0.5f / sig;
        slnc[t] = -ls - HALF_LN_2PI;
    }
    __syncthreads();

    // ---- activation a ----
    if (t == 0) {
        float lsum = 0.f;
        #pragma unroll
        for (int h = 0; h < NV; h++) lsum += sls[h];
        int c = j / PP;
        float cost = (16.0f * beta_v[c] + lsum) * ssumR;
        float x = LAMBDA_C * (beta_a[c] - cost);
        sa = 1.0f / (1.0f + __expf(-x));
    }
    __syncthreads();

    if (MODE < 2) {
        // ---- E-step: ap[b,i,j] = a * sum_h exp(ln_p) ----
        float a = sa;
        float* apw = g_ap + b * (BKK * CWW) + j;
        for (int i = t; i < BKK; i += 256) {
            float p = 0.f;
            #pragma unroll
            for (int h = 0; h < NV; h++) {
                float d = sv[i * 17 + h] - smu[h];
                p += __expf((d * d + EPSV) * sn2s[h] + slnc[h]);
            }
            apw[i * CWW] = a * p;
        }
    } else {
        // ---- final outputs ----
        float* rout = out + R_OFF + b * (BKK * CWW) + j;
        for (int i = t; i < BKK; i += 256)
            rout[i * CWW] = sRw[i];                 // returned R == Rw of iter 2
        if (t < HH) {
            int c = j / PP, p = j - c * PP;
            float v = (t < NV) ? smu[t] : sa;
            out[MU_A_OFF + ((b * NCAP + c) * PP + p) * HH + t] = v;
        }
    }
}

// ---------------------------------------------------------------------------
// S[b,i] = sum_j ap[b,i,j]   (row-contiguous: trivial coalesced reduction)
// ---------------------------------------------------------------------------
__global__ __launch_bounds__(128)
void sum_over_j()
{
    int row = blockIdx.x;                   // b*BKK + i, 0..2303
    const float* ap = g_ap + row * CWW;
    float s = 0.f;
    #pragma unroll
    for (int k = 0; k < CWW / 128; k++)
        s += ap[threadIdx.x + k * 128];
    #pragma unroll
    for (int o = 16; o; o >>= 1) s += __shfl_down_sync(0xffffffffu, s, o);
    __shared__ float r[4];
    if ((threadIdx.x & 31) == 0) r[threadIdx.x >> 5] = s;
    __syncthreads();
    if (threadIdx.x == 0) g_S[row] = r[0] + r[1] + r[2] + r[3];
}

// ---------------------------------------------------------------------------
extern "C" void kernel_launch(void* const* d_in, const int* in_sizes, int n_in,
                              void* d_out, int out_size)
{
    const float* votes  = (const float*)d_in[0];
    const float* beta_v = (const float*)d_in[1];
    const float* beta_a = (const float*)d_in[2];
    float* out = (float*)d_out;

    dim3 grid(CWW, B);

    mstep<0><<<grid, 256>>>(votes, beta_v, beta_a, out);   // iter 0 + votes copy
    sum_over_j<<<B * BKK, 128>>>();                        // S0
    mstep<1><<<grid, 256>>>(votes, beta_v, beta_a, out);   // iter 1
    sum_over_j<<<B * BKK, 128>>>();                        // S1
    mstep<2><<<grid, 256>>>(votes, beta_v, beta_a, out);   // iter 2 + outputs
}

// round 5
// speedup vs baseline: 1.6594x; 1.6594x over previous
#include <cuda_runtime.h>

// ---------------------------------------------------------------------------
// MatrixRouting (EM routing): b=8, Bkk=288, Cww=1152, hh=17, C=32, w=6, 3 iters
// d_out = [ mu_a (8,32,6,6,17) | R (8,288,32,6,6) | votes passthrough ]
// One CTA per (b, j-pair): column data lives in smem; votes read once/iter.
// ---------------------------------------------------------------------------

#define EPSV        1e-10f
#define LAMBDA_C    1e-4f
#define HALF_LN_2PI 0.918938533204672741780329736406f
#define LOG2E       1.44269504088896340736f

constexpr int B    = 8;
constexpr int BKK  = 288;
constexpr int CWW  = 1152;
constexpr int HH   = 17;
constexpr int NV   = 16;
constexpr int NCAP = 32;
constexpr int PP   = 36;

constexpr int MU_A_SIZE = B * NCAP * PP * HH;   // 156672
constexpr int R_SIZE    = B * BKK * CWW;        // 2654208
constexpr int MU_A_OFF  = 0;
constexpr int R_OFF     = MU_A_SIZE;
constexpr int VOTES_OFF = MU_A_SIZE + R_SIZE;

constexpr int ROW2 = CWW * HH / 2;              // row stride in float2 = 9792

// scratch (no cudaMalloc allowed)
__device__ float g_ap[B * BKK * CWW];           // ap, layout (b, i, j)
__device__ float g_S[2][B * BKK];               // ping-pong sum_j ap

__global__ void init_S()
{
    int t = blockIdx.x * 256 + threadIdx.x;
    if (t < 2 * B * BKK) ((float*)g_S)[t] = 0.f;
}

// ---------------------------------------------------------------------------
// MODE 0: R = 1/32; fuses votes passthrough; writes ap + atomics into S[0]
// MODE 1: R from ap/S[0]; writes ap + atomics into S[1]
// MODE 2: R from ap/S[1]; writes mu_a and R_out (= R*a_ of final iter)
// 512 threads = 2 x 256 (one 256-half per j column). TJ=2, j0 even -> float2.
// ---------------------------------------------------------------------------
template <int MODE>
__global__ __launch_bounds__(512, 4)
void mstep(const float2* __restrict__ votes2,
           const float*  __restrict__ beta_v,
           const float*  __restrict__ beta_a,
           float* __restrict__ out)
{
    __shared__ float sv[BKK * 34];      // [i][34]: cols jj*17+h (h=16 -> a_)
    __shared__ float sRw[2 * BKK];      // [jj][i] = R * a_
    __shared__ float spart[512];        // [jj][g][h]
    __shared__ float smu[2][16];
    __shared__ float sn2s[2][16];       // (-1/(2 sigma^2)) * log2e
    __shared__ float slnc[2][16];       // (-log_sigma - 0.5 ln2pi) * log2e
    __shared__ float sls[2][16];        // log_sigma
    __shared__ float ssumR[2];
    __shared__ float sa[2];

    const int j0 = blockIdx.x * 2;      // even
    const int b  = blockIdx.y;
    const int t  = threadIdx.x;
    const int jj = t >> 8;
    const int tt = t & 255;

    // element base /2 : b*(BKK*CWW*HH) + j0*HH, both even
    const int base2 = (b * (BKK * CWW * HH) + j0 * HH) >> 1;

    // ---- load 2 columns into smem as float2 (passthrough copy on MODE 0) ----
    float2* vout2 = (float2*)(out + VOTES_OFF);
    for (int e = t; e < BKK * 17; e += 512) {
        int i = e / 17;
        int q = e - i * 17;
        int g2 = base2 + i * ROW2 + q;
        float2 v = votes2[g2];
        *(float2*)&sv[i * 34 + 2 * q] = v;
        if (MODE == 0) vout2[g2] = v;
    }
    __syncthreads();

    // ---- Rw = R * a_ ----
    const float* apcol = g_ap + b * (BKK * CWW) + j0;
    const float* Sprev = g_S[MODE == 2 ? 1 : 0] + b * BKK;
    for (int i = tt; i < BKK; i += 256) {
        float av = sv[i * 34 + jj * 17 + 16];
        float r;
        if (MODE == 0) {
            r = av * (1.0f / 32.0f);
        } else {
            float ap = apcol[i * CWW + jj];
            float S  = Sprev[i];
            r = (ap / (S + EPSV) + EPSV) * av;
        }
        sRw[jj * BKK + i] = r;
    }
    __syncthreads();

    // ---- mu numerators: per (jj,h), 16 groups over i ----
    {
        int h = tt & 15, g = tt >> 4;
        const float* col = sv + jj * 17 + h;
        const float* rw  = sRw + jj * BKK;
        float acc = 0.f;
        #pragma unroll 6
        for (int i = g; i < BKK; i += 16)
            acc += rw[i] * col[i * 34];
        spart[t] = acc;
    }
    __syncthreads();

    if (t < 32) {                       // mu numerator fold
        int jp = t >> 4, h = t & 15;
        float s = 0.f;
        #pragma unroll
        for (int g = 0; g < 16; g++) s += spart[jp * 256 + g * 16 + h];
        smu[jp][h] = s;
    }
    if ((t >> 5) == 2 || (t >> 5) == 3) {  // warps 2,3: sum_R per jj
        int jp = (t >> 5) - 2, l = t & 31;
        const float* rw = sRw + jp * BKK;
        float s = 0.f;
        #pragma unroll 3
        for (int i = l; i < BKK; i += 32) s += rw[i];
        #pragma unroll
        for (int o = 16; o; o >>= 1) s += __shfl_down_sync(0xffffffffu, s, o);
        if (l == 0) ssumR[jp] = s + 1e-4f;
    }
    __syncthreads();
    if (t < 32) smu[t >> 4][t & 15] /= ssumR[t >> 4];
    __syncthreads();

    // ---- sigma^2 ----
    {
        int h = tt & 15, g = tt >> 4;
        const float* col = sv + jj * 17 + h;
        const float* rw  = sRw + jj * BKK;
        float m = smu[jj][h];
        float acc = 0.f;
        #pragma unroll 6
        for (int i = g; i < BKK; i += 16) {
            float d = col[i * 34] - m;
            acc += rw[i] * fmaf(d, d, EPSV);
        }
        spart[t] = acc;
    }
    __syncthreads();

    if (t < 32) {
        int jp = t >> 4, h = t & 15;
        float s = 0.f;
        #pragma unroll
        for (int g = 0; g < 16; g++) s += spart[jp * 256 + g * 16 + h];
        float sig = s / ssumR[jp] + EPSV;
        float ls  = __logf(sqrtf(sig) + EPSV);
        sls[jp][h]  = ls;
        sn2s[jp][h] = (-0.5f / sig) * LOG2E;
        slnc[jp][h] = (-ls - HALF_LN_2PI) * LOG2E;
    }
    __syncthreads();

    if (t < 2) {                        // activation per jj
        float lsum = 0.f;
        #pragma unroll
        for (int h = 0; h < NV; h++) lsum += sls[t][h];
        int c = (j0 + t) / PP;
        float cost = (16.0f * beta_v[c] + lsum) * ssumR[t];
        float x = LAMBDA_C * (beta_a[c] - cost);
        sa[t] = 1.0f / (1.0f + __expf(-x));
    }
    __syncthreads();

    if (MODE < 2) {
        // ---- E-step: ap = a * sum_h exp(ln_p); fused S accumulation ----
        float a = sa[jj];
        float* apw   = g_ap + b * (BKK * CWW) + j0 + jj;
        float* Snext = g_S[MODE == 0 ? 0 : 1] + b * BKK;
        for (int i = tt; i < BKK; i += 256) {
            const float* row = sv + i * 34 + jj * 17;
            float p = 0.f;
            #pragma unroll 4
            for (int h = 0; h < NV; h++) {
                float d = row[h] - smu[jj][h];
                float e = fmaf(fmaf(d, d, EPSV), sn2s[jj][h], slnc[jj][h]);
                float r;
                asm("ex2.approx.ftz.f32 %0, %1;" : "=f"(r) : "f"(e));
                p += r;
            }
            float ap = a * p;
            apw[i * CWW] = ap;
            atomicAdd(&Snext[i], ap);
        }
    } else {
        // ---- final outputs ----
        float* rout = out + R_OFF + b * (BKK * CWW) + j0;
        for (int i = tt; i < BKK; i += 256)
            rout[i * CWW + jj] = sRw[jj * BKK + i];
        if (t < 2 * HH) {
            int jp = t / HH, h = t - jp * HH;
            int j = j0 + jp;
            int c = j / PP, ppos = j - c * PP;
            float v = (h < NV) ? smu[jp][h] : sa[jp];
            out[MU_A_OFF + ((b * NCAP + c) * PP + ppos) * HH + h] = v;
        }
    }
}

// ---------------------------------------------------------------------------
extern "C" void kernel_launch(void* const* d_in, const int* in_sizes, int n_in,
                              void* d_out, int out_size)
{
    const float2* votes2 = (const float2*)d_in[0];
    const float*  beta_v = (const float*)d_in[1];
    const float*  beta_a = (const float*)d_in[2];
    float* out = (float*)d_out;

    dim3 grid(CWW / 2, B);

    init_S<<<(2 * B * BKK + 255) / 256, 256>>>();
    mstep<0><<<grid, 512>>>(votes2, beta_v, beta_a, out);  // iter0 + votes copy
    mstep<1><<<grid, 512>>>(votes2, beta_v, beta_a, out);  // iter1
    mstep<2><<<grid, 512>>>(votes2, beta_v, beta_a, out);  // iter2 + outputs
}

// round 7
// speedup vs baseline: 1.9387x; 1.1683x over previous
#include <cuda_runtime.h>

// ---------------------------------------------------------------------------
// MatrixRouting (EM routing): b=8, Bkk=288, Cww=1152, hh=17, C=32, w=6, 3 iters
// d_out = [ mu_a (8,32,6,6,17) | R (8,288,32,6,6) | votes passthrough ]
// One CTA per (b, j-pair). Scratch ap/S layout is (b, j, i) => coalesced.
// Final R is produced by a tiled transpose kernel.
// ---------------------------------------------------------------------------

#define EPSV        1e-10f
#define LAMBDA_C    1e-4f
#define HALF_LN_2PI 0.918938533204672741780329736406f
#define LOG2E       1.44269504088896340736f

constexpr int B    = 8;
constexpr int BKK  = 288;
constexpr int CWW  = 1152;
constexpr int HH   = 17;
constexpr int NV   = 16;
constexpr int NCAP = 32;
constexpr int PP   = 36;

constexpr int MU_A_SIZE = B * NCAP * PP * HH;   // 156672
constexpr int R_SIZE    = B * BKK * CWW;        // 2654208
constexpr int MU_A_OFF  = 0;
constexpr int R_OFF     = MU_A_SIZE;
constexpr int VOTES_OFF = MU_A_SIZE + R_SIZE;

constexpr int ROW2 = CWW * HH / 2;              // votes row stride in float2

// scratch (no cudaMalloc allowed)
__device__ float g_ap[B * CWW * BKK];           // layout (b, j, i)  [coalesced]
__device__ float g_S[2][B * BKK];               // ping-pong sum_j ap

__global__ void init_S()
{
    int t = blockIdx.x * 256 + threadIdx.x;
    if (t < 2 * B * BKK) ((float*)g_S)[t] = 0.f;
}

// ---------------------------------------------------------------------------
// MODE 0: R = 1/32; fuses votes passthrough; writes ap + atomics into S[0]
// MODE 1: R from ap/S[0]; writes ap + atomics into S[1]
// MODE 2: R from ap/S[1]; writes mu_a; overwrites g_ap with Rw (for transpose)
// 512 threads = 2 x 256 (one half per j column). TJ=2, j0 even -> float2 I/O.
// ---------------------------------------------------------------------------
template <int MODE>
__global__ __launch_bounds__(512, 4)
void mstep(const float2* __restrict__ votes2,
           const float*  __restrict__ beta_v,
           const float*  __restrict__ beta_a,
           float* __restrict__ out)
{
    __shared__ float sv[BKK * 34];      // [i][34]: cols jj*17+h (h=16 -> a_)
    __shared__ float sRw[2 * BKK];      // [jj][i] = R * a_
    __shared__ float sp1[512];          // partial  sum Rw*V
    __shared__ float sp2[512];          // partial  sum Rw*V^2
    __shared__ float smun[2][16];       // mu numerator
    __shared__ float ssq[2][16];        // sum Rw*V^2 (folded)
    __shared__ float smu[2][16];
    __shared__ float sn2s[2][16];       // (-1/(2 sigma^2)) * log2e
    __shared__ float slnc[2][16];       // (-log_sigma - 0.5 ln2pi) * log2e
    __shared__ float ssumR[2];          // raw sum Rw
    __shared__ float sa[2];

    const int j0 = blockIdx.x * 2;      // even
    const int b  = blockIdx.y;
    const int t  = threadIdx.x;
    const int jj = t >> 8;
    const int tt = t & 255;

    const int base2 = (b * (BKK * CWW * HH) + j0 * HH) >> 1;

    // ---- load 2 columns into smem as float2 (passthrough copy on MODE 0) ----
    float2* vout2 = (float2*)(out + VOTES_OFF);
    for (int e = t; e < BKK * 17; e += 512) {
        int i = e / 17;
        int q = e - i * 17;
        int g2 = base2 + i * ROW2 + q;
        float2 v = votes2[g2];
        *(float2*)&sv[i * 34 + 2 * q] = v;
        if (MODE == 0) vout2[g2] = v;
    }
    __syncthreads();

    // ---- Rw = R * a_  (g_ap/g_S reads fully coalesced) ----
    const float* apcol = g_ap + (b * CWW + j0 + jj) * BKK;
    const float* Sprev = g_S[MODE == 2 ? 1 : 0] + b * BKK;
    for (int i = tt; i < BKK; i += 256) {
        float av = sv[i * 34 + jj * 17 + 16];
        float r;
        if (MODE == 0) {
            r = av * (1.0f / 32.0f);
        } else {
            float ap = apcol[i];
            float S  = Sprev[i];
            r = (ap / (S + EPSV) + EPSV) * av;
        }
        sRw[jj * BKK + i] = r;
    }
    __syncthreads();

    // ---- single moments pass: sum Rw*V and sum Rw*V^2 per (jj,h) ----
    {
        int h = tt & 15, g = tt >> 4;
        const float* col = sv + jj * 17 + h;
        const float* rw  = sRw + jj * BKK;
        float a1 = 0.f, a2 = 0.f;
        #pragma unroll 6
        for (int i = g; i < BKK; i += 16) {
            float r  = rw[i];
            float v  = col[i * 34];
            float rv = r * v;
            a1 += rv;
            a2 = fmaf(rv, v, a2);
        }
        sp1[t] = a1;
        sp2[t] = a2;
    }
    __syncthreads();

    // ---- fold partials; raw sum Rw in warps 2,3 ----
    if (t < 32) {
        int jp = t >> 4, h = t & 15;
        float s = 0.f;
        #pragma unroll
        for (int g = 0; g < 16; g++) s += sp1[jp * 256 + g * 16 + h];
        smun[jp][h] = s;
    } else if (t < 64) {
        int u = t - 32, jp = u >> 4, h = u & 15;
        float s = 0.f;
        #pragma unroll
        for (int g = 0; g < 16; g++) s += sp2[jp * 256 + g * 16 + h];
        ssq[jp][h] = s;
    } else if (t < 128) {
        int jp = (t >> 5) - 2, l = t & 31;
        const float* rw = sRw + jp * BKK;
        float s = 0.f;
        #pragma unroll 3
        for (int i = l; i < BKK; i += 32) s += rw[i];
        #pragma unroll
        for (int o = 16; o; o >>= 1) s += __shfl_down_sync(0xffffffffu, s, o);
        if (l == 0) ssumR[jp] = s;
    }
    __syncthreads();

    // ---- mu, sigma, consts, activation (warp 0 only) ----
    if (t < 32) {
        int jp = t >> 4, h = t & 15;
        float Sr = ssumR[jp];
        float Sp = Sr + 1e-4f;
        float n1 = smun[jp][h];
        float mu = n1 / Sp;
        float sig = (ssq[jp][h] - 2.f * mu * n1 + (mu * mu + EPSV) * Sr) / Sp
                    + EPSV;
        float ls = __logf(sqrtf(sig) + EPSV);
        smu[jp][h]  = mu;
        sn2s[jp][h] = (-0.5f / sig) * LOG2E;
        slnc[jp][h] = (-ls - HALF_LN_2PI) * LOG2E;
        float lsum = ls;
        #pragma unroll
        for (int k = 1; k < 16; k <<= 1)
            lsum += __shfl_xor_sync(0xffffffffu, lsum, k);
        if (h == 0) {
            int c = (j0 + jp) / PP;
            float cost = (16.0f * beta_v[c] + lsum) * Sp;
            float x = LAMBDA_C * (beta_a[c] - cost);
            sa[jp] = 1.0f / (1.0f + __expf(-x));
        }
    }
    __syncthreads();

    if (MODE < 2) {
        // ---- E-step: ap = a * sum_h exp(ln_p); fused S accumulation ----
        float a = sa[jj];
        float* apw   = g_ap + (b * CWW + j0 + jj) * BKK;
        float* Snext = g_S[MODE == 0 ? 0 : 1] + b * BKK;
        for (int i = tt; i < BKK; i += 256) {
            const float* row = sv + i * 34 + jj * 17;
            float p = 0.f;
            #pragma unroll 8
            for (int h = 0; h < NV; h++) {
                float d = row[h] - smu[jj][h];
                float e = fmaf(fmaf(d, d, EPSV), sn2s[jj][h], slnc[jj][h]);
                float r;
                asm("ex2.approx.ftz.f32 %0, %1;" : "=f"(r) : "f"(e));
                p += r;
            }
            float ap = a * p;
            apw[i] = ap;                       // coalesced
            atomicAdd(&Snext[i], ap);          // coalesced REDG
        }
    } else {
        // ---- final: stash Rw into g_ap (coalesced); transpose kernel emits R
        float* apw = g_ap + (b * CWW + j0 + jj) * BKK;
        for (int i = tt; i < BKK; i += 256)
            apw[i] = sRw[jj * BKK + i];
        if (t < 2 * HH) {
            int jp = t / HH, h = t - jp * HH;
            int j = j0 + jp;
            int c = j / PP, ppos = j - c * PP;
            float v = (h < NV) ? smu[jp][h] : sa[jp];
            out[MU_A_OFF + ((b * NCAP + c) * PP + ppos) * HH + h] = v;
        }
    }
}

// ---------------------------------------------------------------------------
// R output: transpose g_ap (b, j, i) -> out (b, i, j), 32x32 smem tiles.
// Fully coalesced on both sides.
// ---------------------------------------------------------------------------
__global__ __launch_bounds__(256)
void transposeR(float* __restrict__ out)
{
    __shared__ float tile[32][33];
    const int bb = blockIdx.z;
    const int j0 = blockIdx.x * 32;
    const int i0 = blockIdx.y * 32;
    const int tx = threadIdx.x, ty = threadIdx.y;   // 32 x 8

    const float* src = g_ap + (bb * CWW + j0) * BKK + i0;
    #pragma unroll
    for (int k = 0; k < 32; k += 8)
        tile[ty + k][tx] = src[(ty + k) * BKK + tx];
    __syncthreads();

    float* dst = out + R_OFF + (bb * BKK + i0) * CWW + j0;
    #pragma unroll
    for (int k = 0; k < 32; k += 8)
        dst[(ty + k) * CWW + tx] = tile[tx][ty + k];
}

// ---------------------------------------------------------------------------
extern "C" void kernel_launch(void* const* d_in, const int* in_sizes, int n_in,
                              void* d_out, int out_size)
{
    const float2* votes2 = (const float2*)d_in[0];
    const float*  beta_v = (const float*)d_in[1];
    const float*  beta_a = (const float*)d_in[2];
    float* out = (float*)d_out;

    dim3 grid(CWW / 2, B);

    init_S<<<(2 * B * BKK + 255) / 256, 256>>>();
    mstep<0><<<grid, 512>>>(votes2, beta_v, beta_a, out);  // iter0 + votes copy
    mstep<1><<<grid, 512>>>(votes2, beta_v, beta_a, out);  // iter1
    mstep<2><<<grid, 512>>>(votes2, beta_v, beta_a, out);  // iter2 + mu_a
    transposeR<<<dim3(CWW / 32, BKK / 32, B), dim3(32, 8)>>>(out);
}

// round 11
// speedup vs baseline: 1.9533x; 1.0075x over previous
#include <cuda_runtime.h>

// ---------------------------------------------------------------------------
// MatrixRouting (EM routing): b=8, Bkk=288, Cww=1152, hh=17, C=32, w=6, 3 iters
// d_out = [ mu_a (8,32,6,6,17) | R (8,288,32,6,6) | votes passthrough ]
// One CTA per (b, j-pair). Scratch ap/S layout is (b, j, i) => coalesced.
// smem rows stride 35 (odd) => bank-conflict-free strided access.
// Final R is produced by a tiled transpose kernel.
// ---------------------------------------------------------------------------

#define EPSV        1e-10f
#define LAMBDA_C    1e-4f
#define HALF_LN_2PI 0.918938533204672741780329736406f
#define LOG2E       1.44269504088896340736f

constexpr int B    = 8;
constexpr int BKK  = 288;
constexpr int CWW  = 1152;
constexpr int HH   = 17;
constexpr int NV   = 16;
constexpr int NCAP = 32;
constexpr int PP   = 36;
constexpr int SROW = 35;                        // odd smem row stride (floats)

constexpr int MU_A_SIZE = B * NCAP * PP * HH;   // 156672
constexpr int R_SIZE    = B * BKK * CWW;        // 2654208
constexpr int MU_A_OFF  = 0;
constexpr int R_OFF     = MU_A_SIZE;
constexpr int VOTES_OFF = MU_A_SIZE + R_SIZE;

constexpr int ROW2 = CWW * HH / 2;              // votes row stride in float2

// scratch (no cudaMalloc allowed)
__device__ float g_ap[B * CWW * BKK];           // layout (b, j, i)
__device__ float g_S[2][B * BKK];               // ping-pong sum_j ap

__global__ void init_S()
{
    int t = blockIdx.x * 256 + threadIdx.x;
    if (t < 2 * B * BKK) ((float*)g_S)[t] = 0.f;
}

// ---------------------------------------------------------------------------
// MODE 0: R = 1/32; fuses votes passthrough; writes ap + atomics into S[0]
// MODE 1: R from ap/S[0]; writes ap + atomics into S[1]
// MODE 2: R from ap/S[1]; writes mu_a; stashes Rw into g_ap (for transpose)
// 512 threads = 2 x 256 (one half per j column). TJ=2, j0 even -> float2 I/O.
// ---------------------------------------------------------------------------
template <int MODE>
__global__ __launch_bounds__(512, 4)
void mstep(const float2* __restrict__ votes2,
           const float*  __restrict__ beta_v,
           const float*  __restrict__ beta_a,
           float* __restrict__ out)
{
    __shared__ float sv[BKK * SROW];    // [i][SROW]: cols jj*17+h (h=16 -> a_)
    __shared__ float sRw[2 * BKK];      // [jj][i] = R * a_
    __shared__ float sp1[512];          // partial  sum Rw*V
    __shared__ float sp2[512];          // partial  sum Rw*V^2
    __shared__ float smun[2][16];       // mu numerator
    __shared__ float ssq[2][16];        // sum Rw*V^2 (folded)
    __shared__ float smu[2][16];
    __shared__ float sn2s[2][16];       // (-1/(2 sigma^2)) * log2e
    __shared__ float slnc[2][16];       // (-log_sigma - 0.5 ln2pi) * log2e
    __shared__ float ssumR[2];          // raw sum Rw
    __shared__ float sa[2];

    const int j0 = blockIdx.x * 2;      // even
    const int b  = blockIdx.y;
    const int t  = threadIdx.x;
    const int jj = t >> 8;
    const int tt = t & 255;

    const int base2 = (b * (BKK * CWW * HH) + j0 * HH) >> 1;

    // ---- load 2 columns into smem (passthrough copy on MODE 0) ----
    float2* vout2 = (float2*)(out + VOTES_OFF);
    for (int e = t; e < BKK * 17; e += 512) {
        int i = e / 17;
        int q = e - i * 17;
        int g2 = base2 + i * ROW2 + q;
        float2 v = votes2[g2];
        sv[i * SROW + 2 * q]     = v.x;   // scalar stores: stride-35 rows
        sv[i * SROW + 2 * q + 1] = v.y;
        if (MODE == 0) vout2[g2] = v;
    }
    __syncthreads();

    // ---- Rw = R * a_  (g_ap/g_S reads fully coalesced) ----
    const float* apcol = g_ap + (b * CWW + j0 + jj) * BKK;
    const float* Sprev = g_S[MODE == 2 ? 1 : 0] + b * BKK;
    for (int i = tt; i < BKK; i += 256) {
        float av = sv[i * SROW + jj * 17 + 16];
        float r;
        if (MODE == 0) {
            r = av * (1.0f / 32.0f);
        } else {
            float ap = apcol[i];
            float S  = Sprev[i];
            r = (ap / (S + EPSV) + EPSV) * av;
        }
        sRw[jj * BKK + i] = r;
    }
    __syncthreads();

    // ---- single moments pass: sum Rw*V and sum Rw*V^2 per (jj,h) ----
    {
        int h = tt & 15, g = tt >> 4;
        const float* col = sv + jj * 17 + h;
        const float* rw  = sRw + jj * BKK;
        float a1 = 0.f, a2 = 0.f;
        #pragma unroll 6
        for (int i = g; i < BKK; i += 16) {
            float r  = rw[i];
            float v  = col[i * SROW];
            float rv = r * v;
            a1 += rv;
            a2 = fmaf(rv, v, a2);
        }
        sp1[t] = a1;
        sp2[t] = a2;
    }
    __syncthreads();

    // ---- fold partials; raw sum Rw in warps 2,3 ----
    if (t < 32) {
        int jp = t >> 4, h = t & 15;
        float s = 0.f;
        #pragma unroll
        for (int g = 0; g < 16; g++) s += sp1[jp * 256 + g * 16 + h];
        smun[jp][h] = s;
    } else if (t < 64) {
        int u = t - 32, jp = u >> 4, h = u & 15;
        float s = 0.f;
        #pragma unroll
        for (int g = 0; g < 16; g++) s += sp2[jp * 256 + g * 16 + h];
        ssq[jp][h] = s;
    } else if (t < 128) {
        int jp = (t >> 5) - 2, l = t & 31;
        const float* rw = sRw + jp * BKK;
        float s = 0.f;
        #pragma unroll 3
        for (int i = l; i < BKK; i += 32) s += rw[i];
        #pragma unroll
        for (int o = 16; o; o >>= 1) s += __shfl_down_sync(0xffffffffu, s, o);
        if (l == 0) ssumR[jp] = s;
    }
    __syncthreads();

    // ---- mu, sigma, consts, activation (warp 0 only) ----
    if (t < 32) {
        int jp = t >> 4, h = t & 15;
        float Sr = ssumR[jp];
        float Sp = Sr + 1e-4f;
        float n1 = smun[jp][h];
        float mu = n1 / Sp;
        float sig = (ssq[jp][h] - 2.f * mu * n1 + (mu * mu + EPSV) * Sr) / Sp
                    + EPSV;
        float ls = __logf(sqrtf(sig) + EPSV);
        smu[jp][h]  = mu;
        sn2s[jp][h] = (-0.5f / sig) * LOG2E;
        slnc[jp][h] = (-ls - HALF_LN_2PI) * LOG2E;
        float lsum = ls;
        #pragma unroll
        for (int k = 1; k < 16; k <<= 1)
            lsum += __shfl_xor_sync(0xffffffffu, lsum, k);
        if (h == 0) {
            int c = (j0 + jp) / PP;
            float cost = (16.0f * beta_v[c] + lsum) * Sp;
            float x = LAMBDA_C * (beta_a[c] - cost);
            sa[jp] = 1.0f / (1.0f + __expf(-x));
        }
    }
    __syncthreads();

    if (MODE < 2) {
        // ---- E-step: ap = a * sum_h exp(ln_p); fused S accumulation ----
        float a = sa[jj];
        float* apw   = g_ap + (b * CWW + j0 + jj) * BKK;
        float* Snext = g_S[MODE == 0 ? 0 : 1] + b * BKK;
        for (int i = tt; i < BKK; i += 256) {
            const float* row = sv + i * SROW + jj * 17;
            float p = 0.f;
            #pragma unroll 8
            for (int h = 0; h < NV; h++) {
                float d = row[h] - smu[jj][h];
                float e = fmaf(fmaf(d, d, EPSV), sn2s[jj][h], slnc[jj][h]);
                float r;
                asm("ex2.approx.ftz.f32 %0, %1;" : "=f"(r) : "f"(e));
                p += r;
            }
            float ap = a * p;
            apw[i] = ap;                       // coalesced
            atomicAdd(&Snext[i], ap);          // coalesced REDG
        }
    } else {
        // ---- final: stash Rw into g_ap (coalesced); transpose emits R ----
        float* apw = g_ap + (b * CWW + j0 + jj) * BKK;
        for (int i = tt; i < BKK; i += 256)
            apw[i] = sRw[jj * BKK + i];
        if (t < 2 * HH) {
            int jp = t / HH, h = t - jp * HH;
            int j = j0 + jp;
            int c = j / PP, ppos = j - c * PP;
            float v = (h < NV) ? smu[jp][h] : sa[jp];
            out[MU_A_OFF + ((b * NCAP + c) * PP + ppos) * HH + h] = v;
        }
    }
}

// ---------------------------------------------------------------------------
// R output: transpose g_ap (b, j, i) -> out (b, i, j), 32x32 smem tiles.
// ---------------------------------------------------------------------------
__global__ __launch_bounds__(256)
void transposeR(float* __restrict__ out)
{
    __shared__ float tile[32][33];
    const int bb = blockIdx.z;
    const int j0 = blockIdx.x * 32;
    const int i0 = blockIdx.y * 32;
    const int tx = threadIdx.x, ty = threadIdx.y;   // 32 x 8

    const float* src = g_ap + (bb * CWW + j0) * BKK + i0;
    #pragma unroll
    for (int k = 0; k < 32; k += 8)
        tile[ty + k][tx] = src[(ty + k) * BKK + tx];
    __syncthreads();

    float* dst = out + R_OFF + (bb * BKK + i0) * CWW + j0;
    #pragma unroll
    for (int k = 0; k < 32; k += 8)
        dst[(ty + k) * CWW + tx] = tile[tx][ty + k];
}

// ---------------------------------------------------------------------------
extern "C" void kernel_launch(void* const* d_in, const int* in_sizes, int n_in,
                              void* d_out, int out_size)
{
    const float2* votes2 = (const float2*)d_in[0];
    const float*  beta_v = (const float*)d_in[1];
    const float*  beta_a = (const float*)d_in[2];
    float* out = (float*)d_out;

    dim3 grid(CWW / 2, B);

    init_S<<<(2 * B * BKK + 255) / 256, 256>>>();
    mstep<0><<<grid, 512>>>(votes2, beta_v, beta_a, out);  // iter0 + votes copy
    mstep<1><<<grid, 512>>>(votes2, beta_v, beta_a, out);  // iter1
    mstep<2><<<grid, 512>>>(votes2, beta_v, beta_a, out);  // iter2 + mu_a
    transposeR<<<dim3(CWW / 32, BKK / 32, B), dim3(32, 8)>>>(out);
}